// round 5
// baseline (speedup 1.0000x reference)
#include <cuda_runtime.h>
#include <cuda_bf16.h>
#include <cuda_fp16.h>
#include <math.h>
#include <stdint.h>

#define T_TOK 8192
#define D_DIM 2048
#define F_DIM 5632
#define E_EXP 8
#define R_RANK 16

// ---------------- scratch (device globals; no allocations allowed) ----------
__device__ float g_base1[(size_t)T_TOK * F_DIM];
__device__ float g_base3[(size_t)T_TOK * F_DIM];
__device__ float g_la1 [T_TOK * 2 * R_RANK];
__device__ float g_la3 [T_TOK * 2 * R_RANK];
__device__ float g_la2c[T_TOK * 2 * R_RANK];
__device__ float g_coef[T_TOK * 2];
__device__ int   g_sel [T_TOK * 2];

// fp16 operands: A-side split (hi+lo), B-side hi only
__device__ __half g_xhi [(size_t)T_TOK * D_DIM];
__device__ __half g_xlo [(size_t)T_TOK * D_DIM];
__device__ __half g_w1h [(size_t)F_DIM * D_DIM];
__device__ __half g_w3h [(size_t)F_DIM * D_DIM];
__device__ __half g_w2h [(size_t)D_DIM * F_DIM];
__device__ __half g_gchi[(size_t)T_TOK * F_DIM];
__device__ __half g_gclo[(size_t)T_TOK * F_DIM];

// =================== PTX helpers (sm_80-compatible only) ====================
__device__ __forceinline__ uint32_t smem_u32(const void* p) {
    uint32_t a;
    asm("{ .reg .u64 t; cvta.to.shared.u64 t, %1; cvt.u32.u64 %0, t; }"
        : "=r"(a) : "l"(p));
    return a;
}
__device__ __forceinline__ void cp16(uint32_t dst, const void* src) {
    asm volatile("cp.async.cg.shared.global [%0], [%1], 16;" :: "r"(dst), "l"(src));
}
#define CP_COMMIT() asm volatile("cp.async.commit_group;" ::: "memory")
#define CP_WAIT(n)  asm volatile("cp.async.wait_group %0;" :: "n"(n) : "memory")

__device__ __forceinline__ void ldsm4(uint32_t* r, uint32_t addr) {
    asm volatile("ldmatrix.sync.aligned.m8n8.x4.shared.b16 {%0,%1,%2,%3}, [%4];"
        : "=r"(r[0]), "=r"(r[1]), "=r"(r[2]), "=r"(r[3]) : "r"(addr));
}
__device__ __forceinline__ void mma_f16(float* c, const uint32_t* a,
                                        uint32_t b0, uint32_t b1) {
    asm volatile(
        "mma.sync.aligned.m16n8k16.row.col.f32.f16.f16.f32 "
        "{%0,%1,%2,%3}, {%4,%5,%6,%7}, {%8,%9}, {%0,%1,%2,%3};"
        : "+f"(c[0]), "+f"(c[1]), "+f"(c[2]), "+f"(c[3])
        : "r"(a[0]), "r"(a[1]), "r"(a[2]), "r"(a[3]), "r"(b0), "r"(b1));
}

// =================== fp16 split-A GEMM via mma.sync =========================
// C[M,N] = (Ahi+Alo)[M,K] @ Bh[N,K]^T    (2 mma passes)
// Tile 128x128, BK=32, 256 threads (8 warps, 2x4 grid, 64x32 per warp).
// 3-stage cp.async pipeline, ONE __syncthreads per BK iteration.
#define ST_AHI 0
#define ST_ALO 8192
#define ST_BH  16384
#define STAGE_SZ 24576
#define NSTAGE 3
#define GEMM_SMEM (NSTAGE * STAGE_SZ)

__device__ __forceinline__ uint32_t sw_off(int row, int c) {
    return (uint32_t)(row * 64 + ((c ^ ((row >> 1) & 3)) << 4));
}

__device__ __forceinline__ void copy_arr(uint32_t dst, const __half* src,
                                         int ldk, int tid) {
#pragma unroll
    for (int it = 0; it < 2; it++) {
        int idx = tid + it * 256;
        int row = idx >> 2, c = idx & 3;
        cp16(dst + sw_off(row, c), src + (size_t)row * ldk + c * 8);
    }
}

__device__ __forceinline__ void copy_stage(uint32_t st, const __half* gAhi,
                                           const __half* gAlo, const __half* gBh,
                                           int k0, int K, int tid) {
    copy_arr(st + ST_AHI, gAhi + k0, K, tid);
    copy_arr(st + ST_ALO, gAlo + k0, K, tid);
    copy_arr(st + ST_BH,  gBh  + k0, K, tid);
    CP_COMMIT();
}

__device__ __forceinline__ void ld_frag16(uint32_t arr, int baserow, int kstep,
                                          int lane, uint32_t* r) {
    int tile = lane >> 3, rin = lane & 7;
    int row = baserow + ((tile & 1) << 3) + rin;
    int chunk = (kstep << 1) + (tile >> 1);
    ldsm4(r, arr + sw_off(row, chunk));
}

__global__ void __launch_bounds__(256, 2)
gemm_mma_split(const __half* __restrict__ Ahi, const __half* __restrict__ Alo,
               const __half* __restrict__ Bh,
               float* __restrict__ C, int M, int N, int K) {
    extern __shared__ char smem[];
    uint32_t sb = smem_u32(smem);
    const int tid = threadIdx.x, lane = tid & 31, wid = tid >> 5;
    const int bm = blockIdx.y * 128, bn = blockIdx.x * 128;
    const int warp_m = (wid >> 2) * 64, warp_n = (wid & 3) * 32;
    const int niter = K / 32;

    const __half* gAhi = Ahi + (size_t)bm * K;
    const __half* gAlo = Alo + (size_t)bm * K;
    const __half* gBh  = Bh  + (size_t)bn * K;

    float acc[4][4][4];
#pragma unroll
    for (int i = 0; i < 4; i++)
#pragma unroll
        for (int j = 0; j < 4; j++)
#pragma unroll
            for (int v = 0; v < 4; v++) acc[i][j][v] = 0.f;

    // prologue: stages 0, 1
    copy_stage(sb,            gAhi, gAlo, gBh, 0,  K, tid);
    copy_stage(sb + STAGE_SZ, gAhi, gAlo, gBh, 32, K, tid);

    int sidx = 0;
    for (int i = 0; i < niter; i++) {
        if (i + 1 < niter) CP_WAIT(1); else CP_WAIT(0);
        __syncthreads();
        if (i + 2 < niter) {
            int snext = sidx + 2; if (snext >= NSTAGE) snext -= NSTAGE;
            copy_stage(sb + (uint32_t)snext * STAGE_SZ, gAhi, gAlo, gBh,
                       (i + 2) * 32, K, tid);
        }
        uint32_t st = sb + (uint32_t)sidx * STAGE_SZ;

#pragma unroll
        for (int ks = 0; ks < 2; ks++) {
            uint32_t ahi[4][4], alo[4][4], bh[2][4];
#pragma unroll
            for (int mt = 0; mt < 4; mt++) {
                ld_frag16(st + ST_AHI, warp_m + mt * 16, ks, lane, ahi[mt]);
                ld_frag16(st + ST_ALO, warp_m + mt * 16, ks, lane, alo[mt]);
            }
#pragma unroll
            for (int ng = 0; ng < 2; ng++)
                ld_frag16(st + ST_BH, warp_n + ng * 16, ks, lane, bh[ng]);
#pragma unroll
            for (int mt = 0; mt < 4; mt++) {
#pragma unroll
                for (int nt = 0; nt < 4; nt++) {
                    int ng = nt >> 1, p = nt & 1;
                    mma_f16(acc[mt][nt], ahi[mt], bh[ng][p], bh[ng][2 + p]);
                    mma_f16(acc[mt][nt], alo[mt], bh[ng][p], bh[ng][2 + p]);
                }
            }
        }
        if (++sidx >= NSTAGE) sidx = 0;
    }

    // epilogue
#pragma unroll
    for (int mt = 0; mt < 4; mt++) {
        int row = bm + warp_m + mt * 16 + (lane >> 2);
#pragma unroll
        for (int nt = 0; nt < 4; nt++) {
            int col = bn + warp_n + nt * 8 + (lane & 3) * 2;
            float* p0 = C + (size_t)row * N + col;
            float* p1 = C + (size_t)(row + 8) * N + col;
            *(float2*)p0 = make_float2(acc[mt][nt][0], acc[mt][nt][1]);
            *(float2*)p1 = make_float2(acc[mt][nt][2], acc[mt][nt][3]);
        }
    }
}

// =================== fp32 -> fp16 conversions ===============================
__global__ void split2_kernel(const float* __restrict__ in,
                              __half* __restrict__ hi,
                              __half* __restrict__ lo, int n4) {
    int i = blockIdx.x * blockDim.x + threadIdx.x;
    if (i >= n4) return;
    float4 v = *(const float4*)(in + (size_t)i * 4);
    float f[4] = {v.x, v.y, v.z, v.w};
    __half h[4], l[4];
#pragma unroll
    for (int j = 0; j < 4; j++) {
        h[j] = __float2half(f[j]);
        l[j] = __float2half(f[j] - __half2float(h[j]));
    }
    __half* hp = hi + (size_t)i * 4;
    __half* lp = lo + (size_t)i * 4;
    *(__half2*)(hp)     = __half2(h[0], h[1]);
    *(__half2*)(hp + 2) = __half2(h[2], h[3]);
    *(__half2*)(lp)     = __half2(l[0], l[1]);
    *(__half2*)(lp + 2) = __half2(l[2], l[3]);
}

__global__ void split1_kernel(const float* __restrict__ in,
                              __half* __restrict__ hi, int n4) {
    int i = blockIdx.x * blockDim.x + threadIdx.x;
    if (i >= n4) return;
    float4 v = *(const float4*)(in + (size_t)i * 4);
    __half* hp = hi + (size_t)i * 4;
    *(__half2*)(hp)     = __half2(__float2half(v.x), __float2half(v.y));
    *(__half2*)(hp + 2) = __half2(__float2half(v.z), __float2half(v.w));
}

// ---------------- router ----------------------------------------------------
__global__ void router_kernel(const float* __restrict__ x,
                              const float* __restrict__ gw,
                              float* __restrict__ logits_out, int write_logits) {
    int t    = blockIdx.x * (blockDim.x >> 5) + (threadIdx.x >> 5);
    int lane = threadIdx.x & 31;
    if (t >= T_TOK) return;
    const float* h = x + (size_t)t * D_DIM;
    float acc[E_EXP];
#pragma unroll
    for (int e = 0; e < E_EXP; e++) acc[e] = 0.f;
    for (int d = lane * 4; d < D_DIM; d += 128) {
        float4 hv = *(const float4*)(h + d);
#pragma unroll
        for (int e = 0; e < E_EXP; e++) {
            float4 gv = *(const float4*)(gw + (size_t)e * D_DIM + d);
            acc[e] += hv.x * gv.x + hv.y * gv.y + hv.z * gv.z + hv.w * gv.w;
        }
    }
#pragma unroll
    for (int e = 0; e < E_EXP; e++) {
#pragma unroll
        for (int o = 16; o > 0; o >>= 1)
            acc[e] += __shfl_xor_sync(0xffffffffu, acc[e], o);
    }
    if (lane == 0) {
        if (write_logits) {
#pragma unroll
            for (int e = 0; e < E_EXP; e++)
                logits_out[(size_t)t * E_EXP + e] = acc[e];
        }
        float m = acc[0];
#pragma unroll
        for (int e = 1; e < E_EXP; e++) m = fmaxf(m, acc[e]);
        float p[E_EXP]; float s = 0.f;
#pragma unroll
        for (int e = 0; e < E_EXP; e++) { p[e] = expf(acc[e] - m); s += p[e]; }
        float invs = 1.f / s;
#pragma unroll
        for (int e = 0; e < E_EXP; e++) p[e] *= invs;
        int i0 = 0; float v0 = p[0];
#pragma unroll
        for (int e = 1; e < E_EXP; e++) if (p[e] > v0) { v0 = p[e]; i0 = e; }
        int i1 = -1; float v1 = -1.f;
#pragma unroll
        for (int e = 0; e < E_EXP; e++) {
            if (e == i0) continue;
            if (p[e] > v1) { v1 = p[e]; i1 = e; }
        }
        float inv = 1.f / (v0 + v1);
        g_sel [t * 2 + 0] = i0;  g_sel [t * 2 + 1] = i1;
        g_coef[t * 2 + 0] = v0 * inv;
        g_coef[t * 2 + 1] = v1 * inv;
    }
}

// ---------------- per-pair lora-A projections -------------------------------
__global__ void loraA_kernel(const float* __restrict__ x,
                             const float* __restrict__ A1,
                             const float* __restrict__ A3) {
    int p    = blockIdx.x * (blockDim.x >> 5) + (threadIdx.x >> 5);
    int lane = threadIdx.x & 31;
    if (p >= T_TOK * 2) return;
    int t = p >> 1;
    int e = g_sel[p];
    const float* h  = x  + (size_t)t * D_DIM;
    const float* a1 = A1 + (size_t)e * R_RANK * D_DIM;
    const float* a3 = A3 + (size_t)e * R_RANK * D_DIM;
    float acc1[R_RANK], acc3[R_RANK];
#pragma unroll
    for (int r = 0; r < R_RANK; r++) { acc1[r] = 0.f; acc3[r] = 0.f; }
    for (int d = lane * 4; d < D_DIM; d += 128) {
        float4 hv = *(const float4*)(h + d);
#pragma unroll
        for (int r = 0; r < R_RANK; r++) {
            float4 av = *(const float4*)(a1 + (size_t)r * D_DIM + d);
            acc1[r] += hv.x * av.x + hv.y * av.y + hv.z * av.z + hv.w * av.w;
            float4 cv = *(const float4*)(a3 + (size_t)r * D_DIM + d);
            acc3[r] += hv.x * cv.x + hv.y * cv.y + hv.z * cv.z + hv.w * cv.w;
        }
    }
#pragma unroll
    for (int r = 0; r < R_RANK; r++) {
#pragma unroll
        for (int o = 16; o > 0; o >>= 1) {
            acc1[r] += __shfl_xor_sync(0xffffffffu, acc1[r], o);
            acc3[r] += __shfl_xor_sync(0xffffffffu, acc3[r], o);
        }
    }
    if (lane == 0) {
#pragma unroll
        for (int r = 0; r < R_RANK; r++) {
            g_la1[p * R_RANK + r] = acc1[r];
            g_la3[p * R_RANK + r] = acc3[r];
        }
    }
}

// ---------------- fused gate: fp16 hi/lo gc + lora2-A partials ---------------
__global__ void __launch_bounds__(128)
gate_kernel(const float* __restrict__ B1, const float* __restrict__ B3,
            const float* __restrict__ A2) {
    int t   = blockIdx.x;
    int tid = threadIdx.x;
    __shared__ float s_la1[2][R_RANK];
    __shared__ float s_la3[2][R_RANK];
    if (tid < 32)      s_la1[tid >> 4][tid & 15] = g_la1[t * 32 + tid];
    else if (tid < 64) { int q = tid - 32; s_la3[q >> 4][q & 15] = g_la3[t * 32 + q]; }
    __syncthreads();
    const int   e0 = g_sel[t * 2],  e1 = g_sel[t * 2 + 1];
    const float c0 = g_coef[t * 2], c1 = g_coef[t * 2 + 1];
    const float* b1e0 = B1 + (size_t)e0 * F_DIM * R_RANK;
    const float* b1e1 = B1 + (size_t)e1 * F_DIM * R_RANK;
    const float* b3e0 = B3 + (size_t)e0 * F_DIM * R_RANK;
    const float* b3e1 = B3 + (size_t)e1 * F_DIM * R_RANK;
    const float* a2e0 = A2 + (size_t)e0 * R_RANK * F_DIM;
    const float* a2e1 = A2 + (size_t)e1 * R_RANK * F_DIM;
    const float* base1 = g_base1 + (size_t)t * F_DIM;
    const float* base3 = g_base3 + (size_t)t * F_DIM;
    __half* gch = g_gchi + (size_t)t * F_DIM;
    __half* gcl = g_gclo + (size_t)t * F_DIM;

    float la2a0[R_RANK], la2a1[R_RANK];
#pragma unroll
    for (int r = 0; r < R_RANK; r++) { la2a0[r] = 0.f; la2a1[r] = 0.f; }

    for (int f0 = tid * 4; f0 < F_DIM; f0 += 128 * 4) {
        float4 bv1 = *(const float4*)(base1 + f0);
        float4 bv3 = *(const float4*)(base3 + f0);
        float u1b[4] = {bv1.x, bv1.y, bv1.z, bv1.w};
        float u3b[4] = {bv3.x, bv3.y, bv3.z, bv3.w};
        float g0[4], g1[4];
        __half h4[4], l4[4];
#pragma unroll
        for (int j = 0; j < 4; j++) {
            int f = f0 + j;
            const float* r1e0 = b1e0 + (size_t)f * R_RANK;
            const float* r1e1 = b1e1 + (size_t)f * R_RANK;
            const float* r3e0 = b3e0 + (size_t)f * R_RANK;
            const float* r3e1 = b3e1 + (size_t)f * R_RANK;
            float d10 = 0.f, d11 = 0.f, d30 = 0.f, d31 = 0.f;
#pragma unroll
            for (int r = 0; r < R_RANK; r += 4) {
                float4 w;
                w = *(const float4*)(r1e0 + r);
                d10 += s_la1[0][r]*w.x + s_la1[0][r+1]*w.y + s_la1[0][r+2]*w.z + s_la1[0][r+3]*w.w;
                w = *(const float4*)(r1e1 + r);
                d11 += s_la1[1][r]*w.x + s_la1[1][r+1]*w.y + s_la1[1][r+2]*w.z + s_la1[1][r+3]*w.w;
                w = *(const float4*)(r3e0 + r);
                d30 += s_la3[0][r]*w.x + s_la3[0][r+1]*w.y + s_la3[0][r+2]*w.z + s_la3[0][r+3]*w.w;
                w = *(const float4*)(r3e1 + r);
                d31 += s_la3[1][r]*w.x + s_la3[1][r+1]*w.y + s_la3[1][r+2]*w.z + s_la3[1][r+3]*w.w;
            }
            float u1_0 = u1b[j] + d10, u3_0 = u3b[j] + d30;
            float u1_1 = u1b[j] + d11, u3_1 = u3b[j] + d31;
            float s0 = u1_0 / (1.f + expf(-u1_0));
            float s1 = u1_1 / (1.f + expf(-u1_1));
            g0[j] = s0 * u3_0;
            g1[j] = s1 * u3_1;
            float gcv = c0 * g0[j] + c1 * g1[j];
            h4[j] = __float2half(gcv);
            l4[j] = __float2half(gcv - __half2float(h4[j]));
        }
        *(__half2*)(gch + f0)     = __half2(h4[0], h4[1]);
        *(__half2*)(gch + f0 + 2) = __half2(h4[2], h4[3]);
        *(__half2*)(gcl + f0)     = __half2(l4[0], l4[1]);
        *(__half2*)(gcl + f0 + 2) = __half2(l4[2], l4[3]);
#pragma unroll
        for (int r = 0; r < R_RANK; r++) {
            float4 av0 = *(const float4*)(a2e0 + (size_t)r * F_DIM + f0);
            la2a0[r] += g0[0]*av0.x + g0[1]*av0.y + g0[2]*av0.z + g0[3]*av0.w;
            float4 av1 = *(const float4*)(a2e1 + (size_t)r * F_DIM + f0);
            la2a1[r] += g1[0]*av1.x + g1[1]*av1.y + g1[2]*av1.z + g1[3]*av1.w;
        }
    }
    int lane = tid & 31, wid = tid >> 5;
#pragma unroll
    for (int r = 0; r < R_RANK; r++) {
#pragma unroll
        for (int o = 16; o > 0; o >>= 1) {
            la2a0[r] += __shfl_xor_sync(0xffffffffu, la2a0[r], o);
            la2a1[r] += __shfl_xor_sync(0xffffffffu, la2a1[r], o);
        }
    }
    __shared__ float red[4][32];
    if (lane == 0) {
#pragma unroll
        for (int r = 0; r < R_RANK; r++) {
            red[wid][r]          = la2a0[r];
            red[wid][R_RANK + r] = la2a1[r];
        }
    }
    __syncthreads();
    if (tid < 32) {
        float v = red[0][tid] + red[1][tid] + red[2][tid] + red[3][tid];
        float c = (tid < R_RANK) ? c0 : c1;
        g_la2c[t * 32 + tid] = v * c;
    }
}

// ---------------- out += sum_k la2c[p_k] @ B2[e_k]^T -------------------------
__global__ void lora2_out_kernel(const float* __restrict__ B2,
                                 float* __restrict__ out) {
    int t   = blockIdx.x;
    int tid = threadIdx.x;
    __shared__ float s_l2[32];
    if (tid < 32) s_l2[tid] = g_la2c[t * 32 + tid];
    __syncthreads();
    int e0 = g_sel[t * 2], e1 = g_sel[t * 2 + 1];
    const float* b2e0 = B2 + (size_t)e0 * D_DIM * R_RANK;
    const float* b2e1 = B2 + (size_t)e1 * D_DIM * R_RANK;
    for (int d = tid; d < D_DIM; d += 256) {
        float s = 0.f;
#pragma unroll
        for (int r = 0; r < R_RANK; r += 4) {
            float4 v0 = *(const float4*)(b2e0 + (size_t)d * R_RANK + r);
            s += s_l2[r]*v0.x + s_l2[r+1]*v0.y + s_l2[r+2]*v0.z + s_l2[r+3]*v0.w;
            float4 v1 = *(const float4*)(b2e1 + (size_t)d * R_RANK + r);
            s += s_l2[16+r]*v1.x + s_l2[16+r+1]*v1.y + s_l2[16+r+2]*v1.z + s_l2[16+r+3]*v1.w;
        }
        out[(size_t)t * D_DIM + d] += s;
    }
}

// ---------------- launch ----------------------------------------------------
extern "C" void kernel_launch(void* const* d_in, const int* in_sizes, int n_in,
                              void* d_out, int out_size) {
    (void)in_sizes; (void)n_in;
    const float* x  = (const float*)d_in[0];
    const float* gw = (const float*)d_in[1];
    const float* W1 = (const float*)d_in[2];
    const float* W3 = (const float*)d_in[3];
    const float* W2 = (const float*)d_in[4];
    const float* A1 = (const float*)d_in[5];
    const float* B1 = (const float*)d_in[6];
    const float* A3 = (const float*)d_in[7];
    const float* B3 = (const float*)d_in[8];
    const float* A2 = (const float*)d_in[9];
    const float* B2 = (const float*)d_in[10];
    float* out = (float*)d_out;

    int write_logits = (out_size >= T_TOK * D_DIM + T_TOK * E_EXP) ? 1 : 0;
    float* logits = out + (size_t)T_TOK * D_DIM;

    float *base1, *base3;
    __half *xhi, *xlo, *w1h, *w3h, *w2h, *gchi, *gclo;
    cudaGetSymbolAddress((void**)&base1, g_base1);
    cudaGetSymbolAddress((void**)&base3, g_base3);
    cudaGetSymbolAddress((void**)&xhi,  g_xhi);
    cudaGetSymbolAddress((void**)&xlo,  g_xlo);
    cudaGetSymbolAddress((void**)&w1h,  g_w1h);
    cudaGetSymbolAddress((void**)&w3h,  g_w3h);
    cudaGetSymbolAddress((void**)&w2h,  g_w2h);
    cudaGetSymbolAddress((void**)&gchi, g_gchi);
    cudaGetSymbolAddress((void**)&gclo, g_gclo);

    cudaFuncSetAttribute(gemm_mma_split,
                         cudaFuncAttributeMaxDynamicSharedMemorySize, GEMM_SMEM);

    // 1. routing (writes router_logits output)
    router_kernel<<<T_TOK / 8, 256>>>(x, gw, logits, write_logits);

    // 2. fp16 conversions
    {
        int n4;
        n4 = T_TOK * D_DIM / 4;  split2_kernel<<<(n4 + 255) / 256, 256>>>(x,  xhi, xlo, n4);
        n4 = F_DIM * D_DIM / 4;  split1_kernel<<<(n4 + 255) / 256, 256>>>(W1, w1h, n4);
        n4 = F_DIM * D_DIM / 4;  split1_kernel<<<(n4 + 255) / 256, 256>>>(W3, w3h, n4);
        n4 = D_DIM * F_DIM / 4;  split1_kernel<<<(n4 + 255) / 256, 256>>>(W2, w2h, n4);
    }

    // 3. base projections: base1 = h@W1^T, base3 = h@W3^T
    {
        dim3 gUp(F_DIM / 128, T_TOK / 128);
        gemm_mma_split<<<gUp, 256, GEMM_SMEM>>>(xhi, xlo, w1h, base1, T_TOK, F_DIM, D_DIM);
        gemm_mma_split<<<gUp, 256, GEMM_SMEM>>>(xhi, xlo, w3h, base3, T_TOK, F_DIM, D_DIM);
    }

    // 4. per-pair lora-A projections
    loraA_kernel<<<(T_TOK * 2) / 4, 128>>>(x, A1, A3);

    // 5. fused SwiGLU gate + combine (fp16 hi/lo) + g@A2^T
    gate_kernel<<<T_TOK, 128>>>(B1, B3, A2);

    // 6. down projection: out = gc @ W2^T
    {
        dim3 gDn(D_DIM / 128, T_TOK / 128);
        gemm_mma_split<<<gDn, 256, GEMM_SMEM>>>(gchi, gclo, w2h, out, T_TOK, D_DIM, F_DIM);
    }

    // 7. rank-16 lora-2 epilogue
    lora2_out_kernel<<<T_TOK, 256>>>(B2, out);
}

// round 6
// speedup vs baseline: 1.6402x; 1.6402x over previous
#include <cuda_runtime.h>
#include <cuda_bf16.h>
#include <cuda_fp16.h>
#include <math.h>
#include <stdint.h>

#define T_TOK 8192
#define D_DIM 2048
#define F_DIM 5632
#define E_EXP 8
#define R_RANK 16

// ---------------- scratch (device globals; no allocations allowed) ----------
__device__ float g_base1[(size_t)T_TOK * F_DIM];
__device__ float g_base3[(size_t)T_TOK * F_DIM];
__device__ float g_la1 [T_TOK * 2 * R_RANK];
__device__ float g_la3 [T_TOK * 2 * R_RANK];
__device__ float g_la2c[T_TOK * 2 * R_RANK];
__device__ float g_coef[T_TOK * 2];
__device__ int   g_sel [T_TOK * 2];

// fp16 operands: A-side split (hi+lo), B-side hi only
__device__ __half g_xhi [(size_t)T_TOK * D_DIM];
__device__ __half g_xlo [(size_t)T_TOK * D_DIM];
__device__ __half g_w1h [(size_t)F_DIM * D_DIM];
__device__ __half g_w3h [(size_t)F_DIM * D_DIM];
__device__ __half g_w2h [(size_t)D_DIM * F_DIM];
__device__ __half g_gchi[(size_t)T_TOK * F_DIM];
__device__ __half g_gclo[(size_t)T_TOK * F_DIM];

// =================== PTX helpers (sm_80-compatible only) ====================
__device__ __forceinline__ uint32_t smem_u32(const void* p) {
    uint32_t a;
    asm("{ .reg .u64 t; cvta.to.shared.u64 t, %1; cvt.u32.u64 %0, t; }"
        : "=r"(a) : "l"(p));
    return a;
}
__device__ __forceinline__ void cp16(uint32_t dst, const void* src) {
    asm volatile("cp.async.cg.shared.global [%0], [%1], 16;" :: "r"(dst), "l"(src));
}
#define CP_COMMIT() asm volatile("cp.async.commit_group;" ::: "memory")
#define CP_WAIT(n)  asm volatile("cp.async.wait_group %0;" :: "n"(n) : "memory")

__device__ __forceinline__ void ldsm4(uint32_t* r, uint32_t addr) {
    asm volatile("ldmatrix.sync.aligned.m8n8.x4.shared.b16 {%0,%1,%2,%3}, [%4];"
        : "=r"(r[0]), "=r"(r[1]), "=r"(r[2]), "=r"(r[3]) : "r"(addr));
}
__device__ __forceinline__ void mma_f16(float* c, const uint32_t* a,
                                        uint32_t b0, uint32_t b1) {
    asm volatile(
        "mma.sync.aligned.m16n8k16.row.col.f32.f16.f16.f32 "
        "{%0,%1,%2,%3}, {%4,%5,%6,%7}, {%8,%9}, {%0,%1,%2,%3};"
        : "+f"(c[0]), "+f"(c[1]), "+f"(c[2]), "+f"(c[3])
        : "r"(a[0]), "r"(a[1]), "r"(a[2]), "r"(a[3]), "r"(b0), "r"(b1));
}

// =================== fp16 split-A GEMM via mma.sync =========================
// C[M,N] = (Ahi+Alo)[M,K] @ Bh[N,K]^T    (2 mma passes)
// Tile 128x128, BK=64, 256 threads (8 warps, 2x4 grid, 64x32 per warp).
// 2-stage cp.async pipeline (R4 structure, proven), halved barrier count.
// SMEM/stage: 3 arrays x 128 rows x 128B = 48KB; double buffered = 96KB.
#define ST_AHI 0
#define ST_ALO 16384
#define ST_BH  32768
#define STAGE_SZ 49152
#define GEMM_SMEM (2 * STAGE_SZ)

// smem layout: K-major rows of 128B (64 fp16); chunk c in 0..7, 8-way swizzle
__device__ __forceinline__ uint32_t sw_off(int row, int c) {
    return (uint32_t)((row << 7) + ((c ^ (row & 7)) << 4));
}

__device__ __forceinline__ void copy_arr(uint32_t dst, const __half* src,
                                         int ldk, int tid) {
#pragma unroll
    for (int it = 0; it < 4; it++) {
        int idx = tid + it * 256;           // 1024 chunks = 128 rows x 8
        int row = idx >> 3, c = idx & 7;
        cp16(dst + sw_off(row, c), src + (size_t)row * ldk + c * 8);
    }
}

// ldmatrix x4 over a 16x16 fp16 region (rows = m or n, cols = k)
__device__ __forceinline__ void ld_frag16(uint32_t arr, int baserow, int kstep,
                                          int lane, uint32_t* r) {
    int tile = lane >> 3, rin = lane & 7;
    int row = baserow + ((tile & 1) << 3) + rin;
    int chunk = (kstep << 1) + (tile >> 1);
    ldsm4(r, arr + sw_off(row, chunk));
}

__global__ void __launch_bounds__(256, 2)
gemm_mma_split(const __half* __restrict__ Ahi, const __half* __restrict__ Alo,
               const __half* __restrict__ Bh,
               float* __restrict__ C, int M, int N, int K) {
    extern __shared__ char smem[];
    uint32_t sb = smem_u32(smem);
    const int tid = threadIdx.x, lane = tid & 31, wid = tid >> 5;
    const int bm = blockIdx.y * 128, bn = blockIdx.x * 128;
    const int warp_m = (wid >> 2) * 64, warp_n = (wid & 3) * 32;
    const int niter = K / 64;

    const __half* gAhi = Ahi + (size_t)bm * K;
    const __half* gAlo = Alo + (size_t)bm * K;
    const __half* gBh  = Bh  + (size_t)bn * K;

    float acc[4][4][4];
#pragma unroll
    for (int i = 0; i < 4; i++)
#pragma unroll
        for (int j = 0; j < 4; j++)
#pragma unroll
            for (int v = 0; v < 4; v++) acc[i][j][v] = 0.f;

    // prologue: stage 0
    {
        uint32_t st = sb;
        copy_arr(st + ST_AHI, gAhi, K, tid);
        copy_arr(st + ST_ALO, gAlo, K, tid);
        copy_arr(st + ST_BH,  gBh,  K, tid);
        CP_COMMIT();
    }

    for (int i = 0; i < niter; i++) {
        uint32_t st = sb + (uint32_t)(i & 1) * STAGE_SZ;
        if (i + 1 < niter) {
            uint32_t stn = sb + (uint32_t)((i + 1) & 1) * STAGE_SZ;
            int k0 = (i + 1) * 64;
            copy_arr(stn + ST_AHI, gAhi + k0, K, tid);
            copy_arr(stn + ST_ALO, gAlo + k0, K, tid);
            copy_arr(stn + ST_BH,  gBh  + k0, K, tid);
            CP_COMMIT();
            CP_WAIT(1);
        } else {
            CP_WAIT(0);
        }
        __syncthreads();

#pragma unroll
        for (int ks = 0; ks < 4; ks++) {
            uint32_t ahi[4][4], alo[4][4], bh[2][4];
#pragma unroll
            for (int mt = 0; mt < 4; mt++) {
                ld_frag16(st + ST_AHI, warp_m + mt * 16, ks, lane, ahi[mt]);
                ld_frag16(st + ST_ALO, warp_m + mt * 16, ks, lane, alo[mt]);
            }
#pragma unroll
            for (int ng = 0; ng < 2; ng++)
                ld_frag16(st + ST_BH, warp_n + ng * 16, ks, lane, bh[ng]);
#pragma unroll
            for (int mt = 0; mt < 4; mt++) {
#pragma unroll
                for (int nt = 0; nt < 4; nt++) {
                    int ng = nt >> 1, p = nt & 1;
                    mma_f16(acc[mt][nt], ahi[mt], bh[ng][p], bh[ng][2 + p]);
                    mma_f16(acc[mt][nt], alo[mt], bh[ng][p], bh[ng][2 + p]);
                }
            }
        }
        __syncthreads();
    }

    // epilogue
#pragma unroll
    for (int mt = 0; mt < 4; mt++) {
        int row = bm + warp_m + mt * 16 + (lane >> 2);
#pragma unroll
        for (int nt = 0; nt < 4; nt++) {
            int col = bn + warp_n + nt * 8 + (lane & 3) * 2;
            float* p0 = C + (size_t)row * N + col;
            float* p1 = C + (size_t)(row + 8) * N + col;
            *(float2*)p0 = make_float2(acc[mt][nt][0], acc[mt][nt][1]);
            *(float2*)p1 = make_float2(acc[mt][nt][2], acc[mt][nt][3]);
        }
    }
}

// =================== fp32 -> fp16 conversions ===============================
__global__ void split2_kernel(const float* __restrict__ in,
                              __half* __restrict__ hi,
                              __half* __restrict__ lo, int n4) {
    int i = blockIdx.x * blockDim.x + threadIdx.x;
    if (i >= n4) return;
    float4 v = *(const float4*)(in + (size_t)i * 4);
    float f[4] = {v.x, v.y, v.z, v.w};
    __half h[4], l[4];
#pragma unroll
    for (int j = 0; j < 4; j++) {
        h[j] = __float2half(f[j]);
        l[j] = __float2half(f[j] - __half2float(h[j]));
    }
    __half* hp = hi + (size_t)i * 4;
    __half* lp = lo + (size_t)i * 4;
    *(__half2*)(hp)     = __half2(h[0], h[1]);
    *(__half2*)(hp + 2) = __half2(h[2], h[3]);
    *(__half2*)(lp)     = __half2(l[0], l[1]);
    *(__half2*)(lp + 2) = __half2(l[2], l[3]);
}

__global__ void split1_kernel(const float* __restrict__ in,
                              __half* __restrict__ hi, int n4) {
    int i = blockIdx.x * blockDim.x + threadIdx.x;
    if (i >= n4) return;
    float4 v = *(const float4*)(in + (size_t)i * 4);
    __half* hp = hi + (size_t)i * 4;
    *(__half2*)(hp)     = __half2(__float2half(v.x), __float2half(v.y));
    *(__half2*)(hp + 2) = __half2(__float2half(v.z), __float2half(v.w));
}

// ---------------- router ----------------------------------------------------
__global__ void router_kernel(const float* __restrict__ x,
                              const float* __restrict__ gw,
                              float* __restrict__ logits_out, int write_logits) {
    int t    = blockIdx.x * (blockDim.x >> 5) + (threadIdx.x >> 5);
    int lane = threadIdx.x & 31;
    if (t >= T_TOK) return;
    const float* h = x + (size_t)t * D_DIM;
    float acc[E_EXP];
#pragma unroll
    for (int e = 0; e < E_EXP; e++) acc[e] = 0.f;
    for (int d = lane * 4; d < D_DIM; d += 128) {
        float4 hv = *(const float4*)(h + d);
#pragma unroll
        for (int e = 0; e < E_EXP; e++) {
            float4 gv = *(const float4*)(gw + (size_t)e * D_DIM + d);
            acc[e] += hv.x * gv.x + hv.y * gv.y + hv.z * gv.z + hv.w * gv.w;
        }
    }
#pragma unroll
    for (int e = 0; e < E_EXP; e++) {
#pragma unroll
        for (int o = 16; o > 0; o >>= 1)
            acc[e] += __shfl_xor_sync(0xffffffffu, acc[e], o);
    }
    if (lane == 0) {
        if (write_logits) {
#pragma unroll
            for (int e = 0; e < E_EXP; e++)
                logits_out[(size_t)t * E_EXP + e] = acc[e];
        }
        float m = acc[0];
#pragma unroll
        for (int e = 1; e < E_EXP; e++) m = fmaxf(m, acc[e]);
        float p[E_EXP]; float s = 0.f;
#pragma unroll
        for (int e = 0; e < E_EXP; e++) { p[e] = expf(acc[e] - m); s += p[e]; }
        float invs = 1.f / s;
#pragma unroll
        for (int e = 0; e < E_EXP; e++) p[e] *= invs;
        int i0 = 0; float v0 = p[0];
#pragma unroll
        for (int e = 1; e < E_EXP; e++) if (p[e] > v0) { v0 = p[e]; i0 = e; }
        int i1 = -1; float v1 = -1.f;
#pragma unroll
        for (int e = 0; e < E_EXP; e++) {
            if (e == i0) continue;
            if (p[e] > v1) { v1 = p[e]; i1 = e; }
        }
        float inv = 1.f / (v0 + v1);
        g_sel [t * 2 + 0] = i0;  g_sel [t * 2 + 1] = i1;
        g_coef[t * 2 + 0] = v0 * inv;
        g_coef[t * 2 + 1] = v1 * inv;
    }
}

// ---------------- per-pair lora-A projections -------------------------------
__global__ void loraA_kernel(const float* __restrict__ x,
                             const float* __restrict__ A1,
                             const float* __restrict__ A3) {
    int p    = blockIdx.x * (blockDim.x >> 5) + (threadIdx.x >> 5);
    int lane = threadIdx.x & 31;
    if (p >= T_TOK * 2) return;
    int t = p >> 1;
    int e = g_sel[p];
    const float* h  = x  + (size_t)t * D_DIM;
    const float* a1 = A1 + (size_t)e * R_RANK * D_DIM;
    const float* a3 = A3 + (size_t)e * R_RANK * D_DIM;
    float acc1[R_RANK], acc3[R_RANK];
#pragma unroll
    for (int r = 0; r < R_RANK; r++) { acc1[r] = 0.f; acc3[r] = 0.f; }
    for (int d = lane * 4; d < D_DIM; d += 128) {
        float4 hv = *(const float4*)(h + d);
#pragma unroll
        for (int r = 0; r < R_RANK; r++) {
            float4 av = *(const float4*)(a1 + (size_t)r * D_DIM + d);
            acc1[r] += hv.x * av.x + hv.y * av.y + hv.z * av.z + hv.w * av.w;
            float4 cv = *(const float4*)(a3 + (size_t)r * D_DIM + d);
            acc3[r] += hv.x * cv.x + hv.y * cv.y + hv.z * cv.z + hv.w * cv.w;
        }
    }
#pragma unroll
    for (int r = 0; r < R_RANK; r++) {
#pragma unroll
        for (int o = 16; o > 0; o >>= 1) {
            acc1[r] += __shfl_xor_sync(0xffffffffu, acc1[r], o);
            acc3[r] += __shfl_xor_sync(0xffffffffu, acc3[r], o);
        }
    }
    if (lane == 0) {
#pragma unroll
        for (int r = 0; r < R_RANK; r++) {
            g_la1[p * R_RANK + r] = acc1[r];
            g_la3[p * R_RANK + r] = acc3[r];
        }
    }
}

// ---------------- fused gate: fp16 hi/lo gc + lora2-A partials ---------------
__global__ void __launch_bounds__(128)
gate_kernel(const float* __restrict__ B1, const float* __restrict__ B3,
            const float* __restrict__ A2) {
    int t   = blockIdx.x;
    int tid = threadIdx.x;
    __shared__ float s_la1[2][R_RANK];
    __shared__ float s_la3[2][R_RANK];
    if (tid < 32)      s_la1[tid >> 4][tid & 15] = g_la1[t * 32 + tid];
    else if (tid < 64) { int q = tid - 32; s_la3[q >> 4][q & 15] = g_la3[t * 32 + q]; }
    __syncthreads();
    const int   e0 = g_sel[t * 2],  e1 = g_sel[t * 2 + 1];
    const float c0 = g_coef[t * 2], c1 = g_coef[t * 2 + 1];
    const float* b1e0 = B1 + (size_t)e0 * F_DIM * R_RANK;
    const float* b1e1 = B1 + (size_t)e1 * F_DIM * R_RANK;
    const float* b3e0 = B3 + (size_t)e0 * F_DIM * R_RANK;
    const float* b3e1 = B3 + (size_t)e1 * F_DIM * R_RANK;
    const float* a2e0 = A2 + (size_t)e0 * R_RANK * F_DIM;
    const float* a2e1 = A2 + (size_t)e1 * R_RANK * F_DIM;
    const float* base1 = g_base1 + (size_t)t * F_DIM;
    const float* base3 = g_base3 + (size_t)t * F_DIM;
    __half* gch = g_gchi + (size_t)t * F_DIM;
    __half* gcl = g_gclo + (size_t)t * F_DIM;

    float la2a0[R_RANK], la2a1[R_RANK];
#pragma unroll
    for (int r = 0; r < R_RANK; r++) { la2a0[r] = 0.f; la2a1[r] = 0.f; }

    for (int f0 = tid * 4; f0 < F_DIM; f0 += 128 * 4) {
        float4 bv1 = *(const float4*)(base1 + f0);
        float4 bv3 = *(const float4*)(base3 + f0);
        float u1b[4] = {bv1.x, bv1.y, bv1.z, bv1.w};
        float u3b[4] = {bv3.x, bv3.y, bv3.z, bv3.w};
        float g0[4], g1[4];
        __half h4[4], l4[4];
#pragma unroll
        for (int j = 0; j < 4; j++) {
            int f = f0 + j;
            const float* r1e0 = b1e0 + (size_t)f * R_RANK;
            const float* r1e1 = b1e1 + (size_t)f * R_RANK;
            const float* r3e0 = b3e0 + (size_t)f * R_RANK;
            const float* r3e1 = b3e1 + (size_t)f * R_RANK;
            float d10 = 0.f, d11 = 0.f, d30 = 0.f, d31 = 0.f;
#pragma unroll
            for (int r = 0; r < R_RANK; r += 4) {
                float4 w;
                w = *(const float4*)(r1e0 + r);
                d10 += s_la1[0][r]*w.x + s_la1[0][r+1]*w.y + s_la1[0][r+2]*w.z + s_la1[0][r+3]*w.w;
                w = *(const float4*)(r1e1 + r);
                d11 += s_la1[1][r]*w.x + s_la1[1][r+1]*w.y + s_la1[1][r+2]*w.z + s_la1[1][r+3]*w.w;
                w = *(const float4*)(r3e0 + r);
                d30 += s_la3[0][r]*w.x + s_la3[0][r+1]*w.y + s_la3[0][r+2]*w.z + s_la3[0][r+3]*w.w;
                w = *(const float4*)(r3e1 + r);
                d31 += s_la3[1][r]*w.x + s_la3[1][r+1]*w.y + s_la3[1][r+2]*w.z + s_la3[1][r+3]*w.w;
            }
            float u1_0 = u1b[j] + d10, u3_0 = u3b[j] + d30;
            float u1_1 = u1b[j] + d11, u3_1 = u3b[j] + d31;
            float s0 = u1_0 / (1.f + expf(-u1_0));
            float s1 = u1_1 / (1.f + expf(-u1_1));
            g0[j] = s0 * u3_0;
            g1[j] = s1 * u3_1;
            float gcv = c0 * g0[j] + c1 * g1[j];
            h4[j] = __float2half(gcv);
            l4[j] = __float2half(gcv - __half2float(h4[j]));
        }
        *(__half2*)(gch + f0)     = __half2(h4[0], h4[1]);
        *(__half2*)(gch + f0 + 2) = __half2(h4[2], h4[3]);
        *(__half2*)(gcl + f0)     = __half2(l4[0], l4[1]);
        *(__half2*)(gcl + f0 + 2) = __half2(l4[2], l4[3]);
#pragma unroll
        for (int r = 0; r < R_RANK; r++) {
            float4 av0 = *(const float4*)(a2e0 + (size_t)r * F_DIM + f0);
            la2a0[r] += g0[0]*av0.x + g0[1]*av0.y + g0[2]*av0.z + g0[3]*av0.w;
            float4 av1 = *(const float4*)(a2e1 + (size_t)r * F_DIM + f0);
            la2a1[r] += g1[0]*av1.x + g1[1]*av1.y + g1[2]*av1.z + g1[3]*av1.w;
        }
    }
    int lane = tid & 31, wid = tid >> 5;
#pragma unroll
    for (int r = 0; r < R_RANK; r++) {
#pragma unroll
        for (int o = 16; o > 0; o >>= 1) {
            la2a0[r] += __shfl_xor_sync(0xffffffffu, la2a0[r], o);
            la2a1[r] += __shfl_xor_sync(0xffffffffu, la2a1[r], o);
        }
    }
    __shared__ float red[4][32];
    if (lane == 0) {
#pragma unroll
        for (int r = 0; r < R_RANK; r++) {
            red[wid][r]          = la2a0[r];
            red[wid][R_RANK + r] = la2a1[r];
        }
    }
    __syncthreads();
    if (tid < 32) {
        float v = red[0][tid] + red[1][tid] + red[2][tid] + red[3][tid];
        float c = (tid < R_RANK) ? c0 : c1;
        g_la2c[t * 32 + tid] = v * c;
    }
}

// ---------------- out += sum_k la2c[p_k] @ B2[e_k]^T -------------------------
__global__ void lora2_out_kernel(const float* __restrict__ B2,
                                 float* __restrict__ out) {
    int t   = blockIdx.x;
    int tid = threadIdx.x;
    __shared__ float s_l2[32];
    if (tid < 32) s_l2[tid] = g_la2c[t * 32 + tid];
    __syncthreads();
    int e0 = g_sel[t * 2], e1 = g_sel[t * 2 + 1];
    const float* b2e0 = B2 + (size_t)e0 * D_DIM * R_RANK;
    const float* b2e1 = B2 + (size_t)e1 * D_DIM * R_RANK;
    for (int d = tid; d < D_DIM; d += 256) {
        float s = 0.f;
#pragma unroll
        for (int r = 0; r < R_RANK; r += 4) {
            float4 v0 = *(const float4*)(b2e0 + (size_t)d * R_RANK + r);
            s += s_l2[r]*v0.x + s_l2[r+1]*v0.y + s_l2[r+2]*v0.z + s_l2[r+3]*v0.w;
            float4 v1 = *(const float4*)(b2e1 + (size_t)d * R_RANK + r);
            s += s_l2[16+r]*v1.x + s_l2[16+r+1]*v1.y + s_l2[16+r+2]*v1.z + s_l2[16+r+3]*v1.w;
        }
        out[(size_t)t * D_DIM + d] += s;
    }
}

// ---------------- launch ----------------------------------------------------
extern "C" void kernel_launch(void* const* d_in, const int* in_sizes, int n_in,
                              void* d_out, int out_size) {
    (void)in_sizes; (void)n_in;
    const float* x  = (const float*)d_in[0];
    const float* gw = (const float*)d_in[1];
    const float* W1 = (const float*)d_in[2];
    const float* W3 = (const float*)d_in[3];
    const float* W2 = (const float*)d_in[4];
    const float* A1 = (const float*)d_in[5];
    const float* B1 = (const float*)d_in[6];
    const float* A3 = (const float*)d_in[7];
    const float* B3 = (const float*)d_in[8];
    const float* A2 = (const float*)d_in[9];
    const float* B2 = (const float*)d_in[10];
    float* out = (float*)d_out;

    int write_logits = (out_size >= T_TOK * D_DIM + T_TOK * E_EXP) ? 1 : 0;
    float* logits = out + (size_t)T_TOK * D_DIM;

    float *base1, *base3;
    __half *xhi, *xlo, *w1h, *w3h, *w2h, *gchi, *gclo;
    cudaGetSymbolAddress((void**)&base1, g_base1);
    cudaGetSymbolAddress((void**)&base3, g_base3);
    cudaGetSymbolAddress((void**)&xhi,  g_xhi);
    cudaGetSymbolAddress((void**)&xlo,  g_xlo);
    cudaGetSymbolAddress((void**)&w1h,  g_w1h);
    cudaGetSymbolAddress((void**)&w3h,  g_w3h);
    cudaGetSymbolAddress((void**)&w2h,  g_w2h);
    cudaGetSymbolAddress((void**)&gchi, g_gchi);
    cudaGetSymbolAddress((void**)&gclo, g_gclo);

    cudaFuncSetAttribute(gemm_mma_split,
                         cudaFuncAttributeMaxDynamicSharedMemorySize, GEMM_SMEM);

    // 1. routing (writes router_logits output)
    router_kernel<<<T_TOK / 8, 256>>>(x, gw, logits, write_logits);

    // 2. fp16 conversions
    {
        int n4;
        n4 = T_TOK * D_DIM / 4;  split2_kernel<<<(n4 + 255) / 256, 256>>>(x,  xhi, xlo, n4);
        n4 = F_DIM * D_DIM / 4;  split1_kernel<<<(n4 + 255) / 256, 256>>>(W1, w1h, n4);
        n4 = F_DIM * D_DIM / 4;  split1_kernel<<<(n4 + 255) / 256, 256>>>(W3, w3h, n4);
        n4 = D_DIM * F_DIM / 4;  split1_kernel<<<(n4 + 255) / 256, 256>>>(W2, w2h, n4);
    }

    // 3. base projections: base1 = h@W1^T, base3 = h@W3^T
    {
        dim3 gUp(F_DIM / 128, T_TOK / 128);
        gemm_mma_split<<<gUp, 256, GEMM_SMEM>>>(xhi, xlo, w1h, base1, T_TOK, F_DIM, D_DIM);
        gemm_mma_split<<<gUp, 256, GEMM_SMEM>>>(xhi, xlo, w3h, base3, T_TOK, F_DIM, D_DIM);
    }

    // 4. per-pair lora-A projections
    loraA_kernel<<<(T_TOK * 2) / 4, 128>>>(x, A1, A3);

    // 5. fused SwiGLU gate + combine (fp16 hi/lo) + g@A2^T
    gate_kernel<<<T_TOK, 128>>>(B1, B3, A2);

    // 6. down projection: out = gc @ W2^T
    {
        dim3 gDn(D_DIM / 128, T_TOK / 128);
        gemm_mma_split<<<gDn, 256, GEMM_SMEM>>>(gchi, gclo, w2h, out, T_TOK, D_DIM, F_DIM);
    }

    // 7. rank-16 lora-2 epilogue
    lora2_out_kernel<<<T_TOK, 256>>>(B2, out);
}

// round 7
// speedup vs baseline: 2.0570x; 1.2541x over previous
#include <cuda_runtime.h>
#include <cuda_bf16.h>
#include <cuda_fp16.h>
#include <math.h>
#include <stdint.h>

#define T_TOK 8192
#define D_DIM 2048
#define F_DIM 5632
#define E_EXP 8
#define R_RANK 16

// ---------------- scratch (device globals; no allocations allowed) ----------
__device__ float g_base1[(size_t)T_TOK * F_DIM];
__device__ float g_base3[(size_t)T_TOK * F_DIM];
__device__ float g_la1 [T_TOK * 2 * R_RANK];
__device__ float g_la3 [T_TOK * 2 * R_RANK];
__device__ float g_la2c[T_TOK * 2 * R_RANK];
__device__ float g_coef[T_TOK * 2];
__device__ int   g_sel [T_TOK * 2];

// fp16 operands (single precision pass)
__device__ __half g_xh  [(size_t)T_TOK * D_DIM];
__device__ __half g_w1h [(size_t)F_DIM * D_DIM];
__device__ __half g_w3h [(size_t)F_DIM * D_DIM];
__device__ __half g_w2h [(size_t)D_DIM * F_DIM];
__device__ __half g_gch [(size_t)T_TOK * F_DIM];

// =================== PTX helpers (sm_80-compatible only) ====================
__device__ __forceinline__ uint32_t smem_u32(const void* p) {
    uint32_t a;
    asm("{ .reg .u64 t; cvta.to.shared.u64 t, %1; cvt.u32.u64 %0, t; }"
        : "=r"(a) : "l"(p));
    return a;
}
__device__ __forceinline__ void cp16(uint32_t dst, const void* src) {
    asm volatile("cp.async.cg.shared.global [%0], [%1], 16;" :: "r"(dst), "l"(src));
}
#define CP_COMMIT() asm volatile("cp.async.commit_group;" ::: "memory")
#define CP_WAIT(n)  asm volatile("cp.async.wait_group %0;" :: "n"(n) : "memory")

__device__ __forceinline__ void ldsm4(uint32_t* r, uint32_t addr) {
    asm volatile("ldmatrix.sync.aligned.m8n8.x4.shared.b16 {%0,%1,%2,%3}, [%4];"
        : "=r"(r[0]), "=r"(r[1]), "=r"(r[2]), "=r"(r[3]) : "r"(addr));
}
__device__ __forceinline__ void mma_f16(float* c, const uint32_t* a,
                                        uint32_t b0, uint32_t b1) {
    asm volatile(
        "mma.sync.aligned.m16n8k16.row.col.f32.f16.f16.f32 "
        "{%0,%1,%2,%3}, {%4,%5,%6,%7}, {%8,%9}, {%0,%1,%2,%3};"
        : "+f"(c[0]), "+f"(c[1]), "+f"(c[2]), "+f"(c[3])
        : "r"(a[0]), "r"(a[1]), "r"(a[2]), "r"(a[3]), "r"(b0), "r"(b1));
}

// =================== fp16 GEMM via mma.sync (single pass) ===================
// C[M,N] = Ah[M,K] @ Bh[N,K]^T
// Tile 128x128, BK=64, 256 threads (8 warps, 2x4 grid, 64x32 per warp).
// 2-stage cp.async pipeline. SMEM/stage: 2 x 128 rows x 128B = 32KB; x2 = 64KB.
#define ST_AH 0
#define ST_BH 16384
#define STAGE_SZ 32768
#define GEMM_SMEM (2 * STAGE_SZ)

// smem layout: K-major rows of 128B (64 fp16); chunk c in 0..7, 8-way swizzle
__device__ __forceinline__ uint32_t sw_off(int row, int c) {
    return (uint32_t)((row << 7) + ((c ^ (row & 7)) << 4));
}

__device__ __forceinline__ void copy_arr(uint32_t dst, const __half* src,
                                         int ldk, int tid) {
#pragma unroll
    for (int it = 0; it < 4; it++) {
        int idx = tid + it * 256;           // 1024 chunks = 128 rows x 8
        int row = idx >> 3, c = idx & 7;
        cp16(dst + sw_off(row, c), src + (size_t)row * ldk + c * 8);
    }
}

__device__ __forceinline__ void ld_frag16(uint32_t arr, int baserow, int kstep,
                                          int lane, uint32_t* r) {
    int tile = lane >> 3, rin = lane & 7;
    int row = baserow + ((tile & 1) << 3) + rin;
    int chunk = (kstep << 1) + (tile >> 1);
    ldsm4(r, arr + sw_off(row, chunk));
}

__global__ void __launch_bounds__(256, 2)
gemm_mma_f16(const __half* __restrict__ Ah, const __half* __restrict__ Bh,
             float* __restrict__ C, int M, int N, int K) {
    extern __shared__ char smem[];
    uint32_t sb = smem_u32(smem);
    const int tid = threadIdx.x, lane = tid & 31, wid = tid >> 5;
    const int bm = blockIdx.y * 128, bn = blockIdx.x * 128;
    const int warp_m = (wid >> 2) * 64, warp_n = (wid & 3) * 32;
    const int niter = K / 64;

    const __half* gAh = Ah + (size_t)bm * K;
    const __half* gBh = Bh + (size_t)bn * K;

    float acc[4][4][4];
#pragma unroll
    for (int i = 0; i < 4; i++)
#pragma unroll
        for (int j = 0; j < 4; j++)
#pragma unroll
            for (int v = 0; v < 4; v++) acc[i][j][v] = 0.f;

    // prologue: stage 0
    {
        uint32_t st = sb;
        copy_arr(st + ST_AH, gAh, K, tid);
        copy_arr(st + ST_BH, gBh, K, tid);
        CP_COMMIT();
    }

    for (int i = 0; i < niter; i++) {
        uint32_t st = sb + (uint32_t)(i & 1) * STAGE_SZ;
        if (i + 1 < niter) {
            uint32_t stn = sb + (uint32_t)((i + 1) & 1) * STAGE_SZ;
            int k0 = (i + 1) * 64;
            copy_arr(stn + ST_AH, gAh + k0, K, tid);
            copy_arr(stn + ST_BH, gBh + k0, K, tid);
            CP_COMMIT();
            CP_WAIT(1);
        } else {
            CP_WAIT(0);
        }
        __syncthreads();

#pragma unroll
        for (int ks = 0; ks < 4; ks++) {
            uint32_t ah[4][4], bh[2][4];
#pragma unroll
            for (int mt = 0; mt < 4; mt++)
                ld_frag16(st + ST_AH, warp_m + mt * 16, ks, lane, ah[mt]);
#pragma unroll
            for (int ng = 0; ng < 2; ng++)
                ld_frag16(st + ST_BH, warp_n + ng * 16, ks, lane, bh[ng]);
#pragma unroll
            for (int mt = 0; mt < 4; mt++) {
#pragma unroll
                for (int nt = 0; nt < 4; nt++) {
                    int ng = nt >> 1, p = nt & 1;
                    mma_f16(acc[mt][nt], ah[mt], bh[ng][p], bh[ng][2 + p]);
                }
            }
        }
        __syncthreads();
    }

    // epilogue
#pragma unroll
    for (int mt = 0; mt < 4; mt++) {
        int row = bm + warp_m + mt * 16 + (lane >> 2);
#pragma unroll
        for (int nt = 0; nt < 4; nt++) {
            int col = bn + warp_n + nt * 8 + (lane & 3) * 2;
            float* p0 = C + (size_t)row * N + col;
            float* p1 = C + (size_t)(row + 8) * N + col;
            *(float2*)p0 = make_float2(acc[mt][nt][0], acc[mt][nt][1]);
            *(float2*)p1 = make_float2(acc[mt][nt][2], acc[mt][nt][3]);
        }
    }
}

// =================== fp32 -> fp16 conversion ================================
__global__ void split1_kernel(const float* __restrict__ in,
                              __half* __restrict__ hi, int n4) {
    int i = blockIdx.x * blockDim.x + threadIdx.x;
    if (i >= n4) return;
    float4 v = *(const float4*)(in + (size_t)i * 4);
    __half* hp = hi + (size_t)i * 4;
    *(__half2*)(hp)     = __half2(__float2half(v.x), __float2half(v.y));
    *(__half2*)(hp + 2) = __half2(__float2half(v.z), __float2half(v.w));
}

// ---------------- router ----------------------------------------------------
__global__ void router_kernel(const float* __restrict__ x,
                              const float* __restrict__ gw,
                              float* __restrict__ logits_out, int write_logits) {
    int t    = blockIdx.x * (blockDim.x >> 5) + (threadIdx.x >> 5);
    int lane = threadIdx.x & 31;
    if (t >= T_TOK) return;
    const float* h = x + (size_t)t * D_DIM;
    float acc[E_EXP];
#pragma unroll
    for (int e = 0; e < E_EXP; e++) acc[e] = 0.f;
    for (int d = lane * 4; d < D_DIM; d += 128) {
        float4 hv = *(const float4*)(h + d);
#pragma unroll
        for (int e = 0; e < E_EXP; e++) {
            float4 gv = *(const float4*)(gw + (size_t)e * D_DIM + d);
            acc[e] += hv.x * gv.x + hv.y * gv.y + hv.z * gv.z + hv.w * gv.w;
        }
    }
#pragma unroll
    for (int e = 0; e < E_EXP; e++) {
#pragma unroll
        for (int o = 16; o > 0; o >>= 1)
            acc[e] += __shfl_xor_sync(0xffffffffu, acc[e], o);
    }
    if (lane == 0) {
        if (write_logits) {
#pragma unroll
            for (int e = 0; e < E_EXP; e++)
                logits_out[(size_t)t * E_EXP + e] = acc[e];
        }
        float m = acc[0];
#pragma unroll
        for (int e = 1; e < E_EXP; e++) m = fmaxf(m, acc[e]);
        float p[E_EXP]; float s = 0.f;
#pragma unroll
        for (int e = 0; e < E_EXP; e++) { p[e] = expf(acc[e] - m); s += p[e]; }
        float invs = 1.f / s;
#pragma unroll
        for (int e = 0; e < E_EXP; e++) p[e] *= invs;
        int i0 = 0; float v0 = p[0];
#pragma unroll
        for (int e = 1; e < E_EXP; e++) if (p[e] > v0) { v0 = p[e]; i0 = e; }
        int i1 = -1; float v1 = -1.f;
#pragma unroll
        for (int e = 0; e < E_EXP; e++) {
            if (e == i0) continue;
            if (p[e] > v1) { v1 = p[e]; i1 = e; }
        }
        float inv = 1.f / (v0 + v1);
        g_sel [t * 2 + 0] = i0;  g_sel [t * 2 + 1] = i1;
        g_coef[t * 2 + 0] = v0 * inv;
        g_coef[t * 2 + 1] = v1 * inv;
    }
}

// ---------------- per-pair lora-A projections -------------------------------
__global__ void loraA_kernel(const float* __restrict__ x,
                             const float* __restrict__ A1,
                             const float* __restrict__ A3) {
    int p    = blockIdx.x * (blockDim.x >> 5) + (threadIdx.x >> 5);
    int lane = threadIdx.x & 31;
    if (p >= T_TOK * 2) return;
    int t = p >> 1;
    int e = g_sel[p];
    const float* h  = x  + (size_t)t * D_DIM;
    const float* a1 = A1 + (size_t)e * R_RANK * D_DIM;
    const float* a3 = A3 + (size_t)e * R_RANK * D_DIM;
    float acc1[R_RANK], acc3[R_RANK];
#pragma unroll
    for (int r = 0; r < R_RANK; r++) { acc1[r] = 0.f; acc3[r] = 0.f; }
    for (int d = lane * 4; d < D_DIM; d += 128) {
        float4 hv = *(const float4*)(h + d);
#pragma unroll
        for (int r = 0; r < R_RANK; r++) {
            float4 av = *(const float4*)(a1 + (size_t)r * D_DIM + d);
            acc1[r] += hv.x * av.x + hv.y * av.y + hv.z * av.z + hv.w * av.w;
            float4 cv = *(const float4*)(a3 + (size_t)r * D_DIM + d);
            acc3[r] += hv.x * cv.x + hv.y * cv.y + hv.z * cv.z + hv.w * cv.w;
        }
    }
#pragma unroll
    for (int r = 0; r < R_RANK; r++) {
#pragma unroll
        for (int o = 16; o > 0; o >>= 1) {
            acc1[r] += __shfl_xor_sync(0xffffffffu, acc1[r], o);
            acc3[r] += __shfl_xor_sync(0xffffffffu, acc3[r], o);
        }
    }
    if (lane == 0) {
#pragma unroll
        for (int r = 0; r < R_RANK; r++) {
            g_la1[p * R_RANK + r] = acc1[r];
            g_la3[p * R_RANK + r] = acc3[r];
        }
    }
}

// ---------------- fused gate: fp16 gc + lora2-A partials ---------------------
__global__ void __launch_bounds__(128)
gate_kernel(const float* __restrict__ B1, const float* __restrict__ B3,
            const float* __restrict__ A2) {
    int t   = blockIdx.x;
    int tid = threadIdx.x;
    __shared__ float s_la1[2][R_RANK];
    __shared__ float s_la3[2][R_RANK];
    if (tid < 32)      s_la1[tid >> 4][tid & 15] = g_la1[t * 32 + tid];
    else if (tid < 64) { int q = tid - 32; s_la3[q >> 4][q & 15] = g_la3[t * 32 + q]; }
    __syncthreads();
    const int   e0 = g_sel[t * 2],  e1 = g_sel[t * 2 + 1];
    const float c0 = g_coef[t * 2], c1 = g_coef[t * 2 + 1];
    const float* b1e0 = B1 + (size_t)e0 * F_DIM * R_RANK;
    const float* b1e1 = B1 + (size_t)e1 * F_DIM * R_RANK;
    const float* b3e0 = B3 + (size_t)e0 * F_DIM * R_RANK;
    const float* b3e1 = B3 + (size_t)e1 * F_DIM * R_RANK;
    const float* a2e0 = A2 + (size_t)e0 * R_RANK * F_DIM;
    const float* a2e1 = A2 + (size_t)e1 * R_RANK * F_DIM;
    const float* base1 = g_base1 + (size_t)t * F_DIM;
    const float* base3 = g_base3 + (size_t)t * F_DIM;
    __half* gch = g_gch + (size_t)t * F_DIM;

    float la2a0[R_RANK], la2a1[R_RANK];
#pragma unroll
    for (int r = 0; r < R_RANK; r++) { la2a0[r] = 0.f; la2a1[r] = 0.f; }

    for (int f0 = tid * 4; f0 < F_DIM; f0 += 128 * 4) {
        float4 bv1 = *(const float4*)(base1 + f0);
        float4 bv3 = *(const float4*)(base3 + f0);
        float u1b[4] = {bv1.x, bv1.y, bv1.z, bv1.w};
        float u3b[4] = {bv3.x, bv3.y, bv3.z, bv3.w};
        float g0[4], g1[4];
        __half h4[4];
#pragma unroll
        for (int j = 0; j < 4; j++) {
            int f = f0 + j;
            const float* r1e0 = b1e0 + (size_t)f * R_RANK;
            const float* r1e1 = b1e1 + (size_t)f * R_RANK;
            const float* r3e0 = b3e0 + (size_t)f * R_RANK;
            const float* r3e1 = b3e1 + (size_t)f * R_RANK;
            float d10 = 0.f, d11 = 0.f, d30 = 0.f, d31 = 0.f;
#pragma unroll
            for (int r = 0; r < R_RANK; r += 4) {
                float4 w;
                w = *(const float4*)(r1e0 + r);
                d10 += s_la1[0][r]*w.x + s_la1[0][r+1]*w.y + s_la1[0][r+2]*w.z + s_la1[0][r+3]*w.w;
                w = *(const float4*)(r1e1 + r);
                d11 += s_la1[1][r]*w.x + s_la1[1][r+1]*w.y + s_la1[1][r+2]*w.z + s_la1[1][r+3]*w.w;
                w = *(const float4*)(r3e0 + r);
                d30 += s_la3[0][r]*w.x + s_la3[0][r+1]*w.y + s_la3[0][r+2]*w.z + s_la3[0][r+3]*w.w;
                w = *(const float4*)(r3e1 + r);
                d31 += s_la3[1][r]*w.x + s_la3[1][r+1]*w.y + s_la3[1][r+2]*w.z + s_la3[1][r+3]*w.w;
            }
            float u1_0 = u1b[j] + d10, u3_0 = u3b[j] + d30;
            float u1_1 = u1b[j] + d11, u3_1 = u3b[j] + d31;
            float s0 = u1_0 / (1.f + expf(-u1_0));
            float s1 = u1_1 / (1.f + expf(-u1_1));
            g0[j] = s0 * u3_0;
            g1[j] = s1 * u3_1;
            float gcv = c0 * g0[j] + c1 * g1[j];
            h4[j] = __float2half(gcv);
        }
        *(__half2*)(gch + f0)     = __half2(h4[0], h4[1]);
        *(__half2*)(gch + f0 + 2) = __half2(h4[2], h4[3]);
#pragma unroll
        for (int r = 0; r < R_RANK; r++) {
            float4 av0 = *(const float4*)(a2e0 + (size_t)r * F_DIM + f0);
            la2a0[r] += g0[0]*av0.x + g0[1]*av0.y + g0[2]*av0.z + g0[3]*av0.w;
            float4 av1 = *(const float4*)(a2e1 + (size_t)r * F_DIM + f0);
            la2a1[r] += g1[0]*av1.x + g1[1]*av1.y + g1[2]*av1.z + g1[3]*av1.w;
        }
    }
    int lane = tid & 31, wid = tid >> 5;
#pragma unroll
    for (int r = 0; r < R_RANK; r++) {
#pragma unroll
        for (int o = 16; o > 0; o >>= 1) {
            la2a0[r] += __shfl_xor_sync(0xffffffffu, la2a0[r], o);
            la2a1[r] += __shfl_xor_sync(0xffffffffu, la2a1[r], o);
        }
    }
    __shared__ float red[4][32];
    if (lane == 0) {
#pragma unroll
        for (int r = 0; r < R_RANK; r++) {
            red[wid][r]          = la2a0[r];
            red[wid][R_RANK + r] = la2a1[r];
        }
    }
    __syncthreads();
    if (tid < 32) {
        float v = red[0][tid] + red[1][tid] + red[2][tid] + red[3][tid];
        float c = (tid < R_RANK) ? c0 : c1;
        g_la2c[t * 32 + tid] = v * c;
    }
}

// ---------------- out += sum_k la2c[p_k] @ B2[e_k]^T -------------------------
__global__ void lora2_out_kernel(const float* __restrict__ B2,
                                 float* __restrict__ out) {
    int t   = blockIdx.x;
    int tid = threadIdx.x;
    __shared__ float s_l2[32];
    if (tid < 32) s_l2[tid] = g_la2c[t * 32 + tid];
    __syncthreads();
    int e0 = g_sel[t * 2], e1 = g_sel[t * 2 + 1];
    const float* b2e0 = B2 + (size_t)e0 * D_DIM * R_RANK;
    const float* b2e1 = B2 + (size_t)e1 * D_DIM * R_RANK;
    for (int d = tid; d < D_DIM; d += 256) {
        float s = 0.f;
#pragma unroll
        for (int r = 0; r < R_RANK; r += 4) {
            float4 v0 = *(const float4*)(b2e0 + (size_t)d * R_RANK + r);
            s += s_l2[r]*v0.x + s_l2[r+1]*v0.y + s_l2[r+2]*v0.z + s_l2[r+3]*v0.w;
            float4 v1 = *(const float4*)(b2e1 + (size_t)d * R_RANK + r);
            s += s_l2[16+r]*v1.x + s_l2[16+r+1]*v1.y + s_l2[16+r+2]*v1.z + s_l2[16+r+3]*v1.w;
        }
        out[(size_t)t * D_DIM + d] += s;
    }
}

// ---------------- launch ----------------------------------------------------
extern "C" void kernel_launch(void* const* d_in, const int* in_sizes, int n_in,
                              void* d_out, int out_size) {
    (void)in_sizes; (void)n_in;
    const float* x  = (const float*)d_in[0];
    const float* gw = (const float*)d_in[1];
    const float* W1 = (const float*)d_in[2];
    const float* W3 = (const float*)d_in[3];
    const float* W2 = (const float*)d_in[4];
    const float* A1 = (const float*)d_in[5];
    const float* B1 = (const float*)d_in[6];
    const float* A3 = (const float*)d_in[7];
    const float* B3 = (const float*)d_in[8];
    const float* A2 = (const float*)d_in[9];
    const float* B2 = (const float*)d_in[10];
    float* out = (float*)d_out;

    int write_logits = (out_size >= T_TOK * D_DIM + T_TOK * E_EXP) ? 1 : 0;
    float* logits = out + (size_t)T_TOK * D_DIM;

    float *base1, *base3;
    __half *xh, *w1h, *w3h, *w2h, *gch;
    cudaGetSymbolAddress((void**)&base1, g_base1);
    cudaGetSymbolAddress((void**)&base3, g_base3);
    cudaGetSymbolAddress((void**)&xh,   g_xh);
    cudaGetSymbolAddress((void**)&w1h,  g_w1h);
    cudaGetSymbolAddress((void**)&w3h,  g_w3h);
    cudaGetSymbolAddress((void**)&w2h,  g_w2h);
    cudaGetSymbolAddress((void**)&gch,  g_gch);

    cudaFuncSetAttribute(gemm_mma_f16,
                         cudaFuncAttributeMaxDynamicSharedMemorySize, GEMM_SMEM);

    // 1. routing (writes router_logits output)
    router_kernel<<<T_TOK / 8, 256>>>(x, gw, logits, write_logits);

    // 2. fp16 conversions
    {
        int n4;
        n4 = T_TOK * D_DIM / 4;  split1_kernel<<<(n4 + 255) / 256, 256>>>(x,  xh,  n4);
        n4 = F_DIM * D_DIM / 4;  split1_kernel<<<(n4 + 255) / 256, 256>>>(W1, w1h, n4);
        n4 = F_DIM * D_DIM / 4;  split1_kernel<<<(n4 + 255) / 256, 256>>>(W3, w3h, n4);
        n4 = D_DIM * F_DIM / 4;  split1_kernel<<<(n4 + 255) / 256, 256>>>(W2, w2h, n4);
    }

    // 3. base projections: base1 = h@W1^T, base3 = h@W3^T
    {
        dim3 gUp(F_DIM / 128, T_TOK / 128);
        gemm_mma_f16<<<gUp, 256, GEMM_SMEM>>>(xh, w1h, base1, T_TOK, F_DIM, D_DIM);
        gemm_mma_f16<<<gUp, 256, GEMM_SMEM>>>(xh, w3h, base3, T_TOK, F_DIM, D_DIM);
    }

    // 4. per-pair lora-A projections
    loraA_kernel<<<(T_TOK * 2) / 4, 128>>>(x, A1, A3);

    // 5. fused SwiGLU gate + combine (fp16) + g@A2^T
    gate_kernel<<<T_TOK, 128>>>(B1, B3, A2);

    // 6. down projection: out = gc @ W2^T
    {
        dim3 gDn(D_DIM / 128, T_TOK / 128);
        gemm_mma_f16<<<gDn, 256, GEMM_SMEM>>>(gch, w2h, out, T_TOK, D_DIM, F_DIM);
    }

    // 7. rank-16 lora-2 epilogue
    lora2_out_kernel<<<T_TOK, 256>>>(B2, out);
}